// round 2
// baseline (speedup 1.0000x reference)
#include <cuda_runtime.h>
#include <cstdint>

// Problem constants (fixed shapes for SparseMoE_2250562863537)
#define B_TOK   8192
#define L_DIM   1024
#define E_DIM   1024
#define D_DIM   2048
#define N_EXP   8

// Scratch: per-expert token lists + counts (device globals — no allocs allowed)
__device__ int g_cnt[N_EXP];
__device__ int g_list[N_EXP * B_TOK];

// ---------------------------------------------------------------------------
// Kernel 0: zero the per-expert counters (graph replays must be idempotent)
// ---------------------------------------------------------------------------
__global__ void zero_cnt_kernel() {
    if (threadIdx.x < N_EXP) g_cnt[threadIdx.x] = 0;
}

// ---------------------------------------------------------------------------
// Kernel 1: gate logits + argmax + scatter into per-expert token lists.
// One warp per token. gW (64 KB) stays hot in L1/L2.
// topk with K=1 + softmax over 1 element => gate weight is exactly 1.0.
// Tie-break: strict '>' keeps lowest expert index (matches jax.lax.top_k).
// ---------------------------------------------------------------------------
__global__ void gate_kernel(const float* __restrict__ x,
                            const float* __restrict__ y,
                            const float* __restrict__ gW,
                            const float* __restrict__ gb) {
    int gwarp = (blockIdx.x * blockDim.x + threadIdx.x) >> 5;
    int lane  = threadIdx.x & 31;
    if (gwarp >= B_TOK) return;
    int tok = gwarp;

    float acc[N_EXP];
#pragma unroll
    for (int e = 0; e < N_EXP; e++) acc[e] = 0.0f;

    // D = 2048 split across 32 lanes; 1024 % 32 == 0 so the x/y branch is
    // warp-uniform per iteration.
    for (int k = lane; k < D_DIM; k += 32) {
        float v = (k < L_DIM) ? x[(size_t)tok * L_DIM + k]
                              : y[(size_t)tok * E_DIM + (k - L_DIM)];
#pragma unroll
        for (int e = 0; e < N_EXP; e++)
            acc[e] = fmaf(v, gW[e * D_DIM + k], acc[e]);
    }

    // warp reduction
#pragma unroll
    for (int e = 0; e < N_EXP; e++) {
#pragma unroll
        for (int o = 16; o > 0; o >>= 1)
            acc[e] += __shfl_xor_sync(0xFFFFFFFFu, acc[e], o);
    }

    if (lane == 0) {
        float best = acc[0] + gb[0];
        int   bidx = 0;
#pragma unroll
        for (int e = 1; e < N_EXP; e++) {
            float v = acc[e] + gb[e];
            if (v > best) { best = v; bidx = e; }
        }
        int pos = atomicAdd(&g_cnt[bidx], 1);
        g_list[bidx * B_TOK + pos] = tok;
    }
}

// ---------------------------------------------------------------------------
// Kernel 2: grouped SGEMM.  out[tok, :] = inp[tok, :] @ We[e]^T + be[e]
//   We is [E, out(D), in(D)] row-major, so out[n] = sum_k inp[k] * We[e][n][k]
// Tiles: BM=128 tokens x BN=128 outputs x BK=16, 256 threads, 8x8 per thread.
// grid = (64 m-tiles max, 16 n-tiles, 8 experts); empty m-tiles exit early.
// ---------------------------------------------------------------------------
#define BM 128
#define BN 128
#define BK 16

__global__ __launch_bounds__(256, 2)
void moe_gemm_kernel(const float* __restrict__ x,
                     const float* __restrict__ y,
                     const float* __restrict__ We,
                     const float* __restrict__ be,
                     float* __restrict__ out) {
    const int e  = blockIdx.z;
    const int ne = g_cnt[e];
    const int m0 = blockIdx.x * BM;
    if (m0 >= ne) return;                // early-exit empty tiles
    const int n0 = blockIdx.y * BN;

    __shared__ float As[BK][BM + 4];     // k-major, padded
    __shared__ float Bs[BK][BN + 4];
    __shared__ int   rows[BM];

    const int tid = threadIdx.x;

    // Stage token indices for this m-tile (pad with row 0 of the list — the
    // loads are valid, results are masked in the epilogue).
    if (tid < BM) {
        int gm = m0 + tid;
        rows[tid] = (gm < ne) ? g_list[e * B_TOK + gm] : g_list[e * B_TOK];
    }
    __syncthreads();

    const float* W = We + (size_t)e * D_DIM * D_DIM;

    float acc[8][8];
#pragma unroll
    for (int i = 0; i < 8; i++)
#pragma unroll
        for (int j = 0; j < 8; j++) acc[i][j] = 0.0f;

    const int tx = tid & 15;   // output-col group
    const int ty = tid >> 4;   // token-row group

    for (int k0 = 0; k0 < D_DIM; k0 += BK) {
        // ---- load A tile (gathered token rows), 2 float4 per thread ----
#pragma unroll
        for (int u = 0; u < 2; u++) {
            int f  = tid + u * 256;        // float4 id: 0..511
            int r  = f >> 2;               // token row in tile
            int kq = (f & 3) << 2;         // k offset quad: 0,4,8,12
            int tok = rows[r];
            int col = k0 + kq;
            const float* src = (col < L_DIM)
                ? (x + (size_t)tok * L_DIM + col)
                : (y + (size_t)tok * E_DIM + (col - L_DIM));
            float4 v = *reinterpret_cast<const float4*>(src);
            As[kq + 0][r] = v.x;
            As[kq + 1][r] = v.y;
            As[kq + 2][r] = v.z;
            As[kq + 3][r] = v.w;
        }
        // ---- load B tile (expert weight rows), 2 float4 per thread ----
#pragma unroll
        for (int u = 0; u < 2; u++) {
            int f  = tid + u * 256;
            int n  = f >> 2;
            int kq = (f & 3) << 2;
            float4 v = *reinterpret_cast<const float4*>(
                W + (size_t)(n0 + n) * D_DIM + k0 + kq);
            Bs[kq + 0][n] = v.x;
            Bs[kq + 1][n] = v.y;
            Bs[kq + 2][n] = v.z;
            Bs[kq + 3][n] = v.w;
        }
        __syncthreads();

        // ---- compute ----
#pragma unroll
        for (int k = 0; k < BK; k++) {
            float a[8], b[8];
            *reinterpret_cast<float4*>(a)     = *reinterpret_cast<float4*>(&As[k][ty * 8]);
            *reinterpret_cast<float4*>(a + 4) = *reinterpret_cast<float4*>(&As[k][ty * 8 + 4]);
            *reinterpret_cast<float4*>(b)     = *reinterpret_cast<float4*>(&Bs[k][tx * 8]);
            *reinterpret_cast<float4*>(b + 4) = *reinterpret_cast<float4*>(&Bs[k][tx * 8 + 4]);
#pragma unroll
            for (int i = 0; i < 8; i++)
#pragma unroll
                for (int j = 0; j < 8; j++)
                    acc[i][j] = fmaf(a[i], b[j], acc[i][j]);
        }
        __syncthreads();
    }

    // ---- epilogue: add bias, scatter rows back to token positions ----
#pragma unroll
    for (int i = 0; i < 8; i++) {
        int gm = m0 + ty * 8 + i;
        if (gm < ne) {
            int tok = rows[ty * 8 + i];
            float* dst = out + (size_t)tok * D_DIM + n0 + tx * 8;
            const float* bias = be + e * D_DIM + n0 + tx * 8;
#pragma unroll
            for (int j = 0; j < 8; j += 4) {
                float4 v;
                v.x = acc[i][j + 0] + bias[j + 0];
                v.y = acc[i][j + 1] + bias[j + 1];
                v.z = acc[i][j + 2] + bias[j + 2];
                v.w = acc[i][j + 3] + bias[j + 3];
                *reinterpret_cast<float4*>(dst + j) = v;
            }
        }
    }
}

// ---------------------------------------------------------------------------
// Launch
// ---------------------------------------------------------------------------
extern "C" void kernel_launch(void* const* d_in, const int* in_sizes, int n_in,
                              void* d_out, int out_size) {
    const float* x  = (const float*)d_in[0];   // [8192, 1024]
    const float* y  = (const float*)d_in[1];   // [8192, 1024]
    const float* We = (const float*)d_in[2];   // [8, 2048, 2048]
    const float* be = (const float*)d_in[3];   // [8, 2048]
    const float* gW = (const float*)d_in[4];   // [8, 2048]
    const float* gb = (const float*)d_in[5];   // [8]
    float* out = (float*)d_out;                // [8192, 2048]

    zero_cnt_kernel<<<1, 32>>>();

    // one warp per token
    gate_kernel<<<(B_TOK * 32) / 256, 256>>>(x, y, gW, gb);

    // grouped GEMM: worst case all tokens on one expert -> 64 m-tiles
    dim3 grid(B_TOK / BM, D_DIM / BN, N_EXP);
    moe_gemm_kernel<<<grid, 256>>>(x, y, We, be, out);
}

// round 4
// speedup vs baseline: 1.8137x; 1.8137x over previous
#include <cuda_runtime.h>
#include <cuda_bf16.h>
#include <cstdint>

// ---------------------------------------------------------------------------
// SparseMoE_2250562863537:
//   B=8192 tokens, inp = concat(x[.,1024], y[.,1024]) => D=2048, 8 experts,
//   K=1 top-k => softmax over one logit == 1.0
//   => out[b] = We[e_b] @ inp[b] + be[e_b],  e_b = argmax(gW @ inp[b] + gb)
//
// NOTE: build pipeline targets PTX .target sm_103 (no 'a') => tcgen05 is NOT
// available. Use legacy mma.sync.m16n8k16 (bf16, sm_80 baseline) + ldmatrix.
// Precision: fp32 operands split to bf16 hi/lo; 3 passes hi*hi+hi*lo+lo*hi,
// fp32 register accumulators => rel err ~1e-5.
// ---------------------------------------------------------------------------
#define B_TOK   8192
#define L_DIM   1024
#define D_DIM   2048
#define N_EXP   8

#define BM      128
#define BN      128
#define BK      64
#define NKIT    (D_DIM / BK)       // 32
#define THREADS 256                // 8 warps: 2 (m) x 4 (n), warp tile 64x32

// Scratch (device globals — no allocs allowed)
__device__ int g_cnt[N_EXP];
__device__ int g_list[N_EXP * B_TOK];

// ---------------------------------------------------------------------------
// SMEM layout
//   [0,512)    rows[128]
//   [512,1024) bias[128]
//   [1024,...) 2 x 64KB tile buffers, each: A_hi|A_lo|B_hi|B_lo (16KB each)
//   tiles are bf16 [128 rows][64 cols], 128B rows, SW128 xor swizzle
// ---------------------------------------------------------------------------
#define SM_ROWS    0
#define SM_BIAS    512
#define SM_TILES   1024
#define BUF_BYTES  65536
#define OFF_A_HI   0
#define OFF_A_LO   16384
#define OFF_B_HI   32768
#define OFF_B_LO   49152
#define SMEM_TOTAL (SM_TILES + 2 * BUF_BYTES)   // 132096 bytes

#define SWZ(b) ((b) ^ (((b) >> 3) & 0x70))

// ---------------------------------------------------------------------------
// helpers
// ---------------------------------------------------------------------------
__device__ __forceinline__ uint32_t smem_u32(const void* p) {
    uint32_t a;
    asm("{ .reg .u64 t; cvta.to.shared.u64 t, %1; cvt.u32.u64 %0, t; }"
        : "=r"(a) : "l"(p));
    return a;
}

__device__ __forceinline__ void ldsm4(uint32_t* r, uint32_t addr) {
    asm volatile("ldmatrix.sync.aligned.m8n8.x4.shared.b16 {%0,%1,%2,%3}, [%4];"
                 : "=r"(r[0]), "=r"(r[1]), "=r"(r[2]), "=r"(r[3]) : "r"(addr));
}

__device__ __forceinline__ void mma_bf16(float* c, const uint32_t* a,
                                         uint32_t b0, uint32_t b1) {
    asm volatile("mma.sync.aligned.m16n8k16.row.col.f32.bf16.bf16.f32 "
                 "{%0,%1,%2,%3}, {%4,%5,%6,%7}, {%8,%9}, {%0,%1,%2,%3};"
                 : "+f"(c[0]), "+f"(c[1]), "+f"(c[2]), "+f"(c[3])
                 : "r"(a[0]), "r"(a[1]), "r"(a[2]), "r"(a[3]),
                   "r"(b0), "r"(b1));
}

// split fp32x4 -> (hi,lo) bf16x2 pairs
__device__ __forceinline__ void split4(float4 v, uint2& hi, uint2& lo) {
    __nv_bfloat16 h0 = __float2bfloat16(v.x);
    __nv_bfloat16 h1 = __float2bfloat16(v.y);
    __nv_bfloat16 h2 = __float2bfloat16(v.z);
    __nv_bfloat16 h3 = __float2bfloat16(v.w);
    __nv_bfloat16 l0 = __float2bfloat16(v.x - __bfloat162float(h0));
    __nv_bfloat16 l1 = __float2bfloat16(v.y - __bfloat162float(h1));
    __nv_bfloat16 l2 = __float2bfloat16(v.z - __bfloat162float(h2));
    __nv_bfloat16 l3 = __float2bfloat16(v.w - __bfloat162float(h3));
    hi.x = (uint32_t)__bfloat16_as_ushort(h0) | ((uint32_t)__bfloat16_as_ushort(h1) << 16);
    hi.y = (uint32_t)__bfloat16_as_ushort(h2) | ((uint32_t)__bfloat16_as_ushort(h3) << 16);
    lo.x = (uint32_t)__bfloat16_as_ushort(l0) | ((uint32_t)__bfloat16_as_ushort(l1) << 16);
    lo.y = (uint32_t)__bfloat16_as_ushort(l2) | ((uint32_t)__bfloat16_as_ushort(l3) << 16);
}

// ---------------------------------------------------------------------------
// Kernel 0: zero counters
// ---------------------------------------------------------------------------
__global__ void zero_cnt_kernel() {
    if (threadIdx.x < N_EXP) g_cnt[threadIdx.x] = 0;
}

// ---------------------------------------------------------------------------
// Kernel 1: gate + argmax + scatter (proven in R2, rel_err 8e-7)
// ---------------------------------------------------------------------------
__global__ void gate_kernel(const float* __restrict__ x,
                            const float* __restrict__ y,
                            const float* __restrict__ gW,
                            const float* __restrict__ gb) {
    int gwarp = (blockIdx.x * blockDim.x + threadIdx.x) >> 5;
    int lane  = threadIdx.x & 31;
    if (gwarp >= B_TOK) return;
    int tok = gwarp;

    float acc[N_EXP];
#pragma unroll
    for (int e = 0; e < N_EXP; e++) acc[e] = 0.0f;

    for (int k = lane; k < D_DIM; k += 32) {
        float v = (k < L_DIM) ? x[(size_t)tok * L_DIM + k]
                              : y[(size_t)tok * L_DIM + (k - L_DIM)];
#pragma unroll
        for (int e = 0; e < N_EXP; e++)
            acc[e] = fmaf(v, gW[e * D_DIM + k], acc[e]);
    }
#pragma unroll
    for (int e = 0; e < N_EXP; e++) {
#pragma unroll
        for (int o = 16; o > 0; o >>= 1)
            acc[e] += __shfl_xor_sync(0xFFFFFFFFu, acc[e], o);
    }
    if (lane == 0) {
        float best = acc[0] + gb[0];
        int   bidx = 0;
#pragma unroll
        for (int e = 1; e < N_EXP; e++) {
            float v = acc[e] + gb[e];
            if (v > best) { best = v; bidx = e; }
        }
        int pos = atomicAdd(&g_cnt[bidx], 1);
        g_list[bidx * B_TOK + pos] = tok;
    }
}

// ---------------------------------------------------------------------------
// Kernel 2: grouped GEMM, mma.sync bf16x3, fp32 reg accumulators
// ---------------------------------------------------------------------------
__global__ __launch_bounds__(THREADS, 1)
void moe_gemm_mma(const float* __restrict__ x,
                  const float* __restrict__ y,
                  const float* __restrict__ We,
                  const float* __restrict__ be,
                  float* __restrict__ out) {
    const int e  = blockIdx.z;
    const int ne = g_cnt[e];
    const int m0 = blockIdx.x * BM;
    if (m0 >= ne) return;
    const int n0 = blockIdx.y * BN;

    extern __shared__ char smem[];
    const uint32_t sbase = smem_u32(smem);
    int*   rs     = (int*)(smem + SM_ROWS);
    float* bias_s = (float*)(smem + SM_BIAS);

    const int tid    = threadIdx.x;
    const int wid    = tid >> 5;
    const int lane   = tid & 31;
    const int warp_m = wid & 1;    // 0..1 -> m offset 0 / 64
    const int warp_n = wid >> 1;   // 0..3 -> n offset 0/32/64/96

    // ---- stage token rows + bias ----
    if (tid < BM) {
        int gm = m0 + tid;
        rs[tid]     = (gm < ne) ? g_list[e * B_TOK + gm] : g_list[e * B_TOK];
        bias_s[tid] = be[e * D_DIM + n0 + tid];
    }
    __syncthreads();

    const float* W = We + (size_t)e * D_DIM * D_DIM + (size_t)n0 * D_DIM;

    // per-thread tile-load geometry: 16 float4/thread/iter (8 A + 8 B)
    const int ldr  = tid >> 4;          // used with +16*u below? no: see loop
    (void)ldr;

    float4 av[8], bv[8];

    // ---- tile loaders ----
    auto ldg_tile = [&](int kt) {
        const int k0 = kt * BK;
        const float* xa  = (k0 < L_DIM) ? x : y;
        const int   acol = (k0 < L_DIM) ? k0 : (k0 - L_DIM);
#pragma unroll
        for (int u = 0; u < 8; u++) {
            int f  = u * THREADS + tid;   // 0..2047
            int r  = f >> 4;              // row 0..127
            int c4 = f & 15;              // float4 col 0..15
            av[u] = *reinterpret_cast<const float4*>(
                xa + (size_t)rs[r] * L_DIM + acol + c4 * 4);
            bv[u] = *reinterpret_cast<const float4*>(
                W + (size_t)r * D_DIM + k0 + c4 * 4);
        }
    };
    auto sts_tile = [&](int b) {
        char* bufc = smem + SM_TILES + b * BUF_BYTES;
#pragma unroll
        for (int u = 0; u < 8; u++) {
            int f  = u * THREADS + tid;
            int r  = f >> 4;
            int c4 = f & 15;
            uint32_t boff = SWZ((uint32_t)(r * 128 + c4 * 8));
            uint2 hv, lv;
            split4(av[u], hv, lv);
            *reinterpret_cast<uint2*>(bufc + OFF_A_HI + boff) = hv;
            *reinterpret_cast<uint2*>(bufc + OFF_A_LO + boff) = lv;
            split4(bv[u], hv, lv);
            *reinterpret_cast<uint2*>(bufc + OFF_B_HI + boff) = hv;
            *reinterpret_cast<uint2*>(bufc + OFF_B_LO + boff) = lv;
        }
    };

    // ---- accumulators ----
    float acc[4][4][4];
#pragma unroll
    for (int i = 0; i < 4; i++)
#pragma unroll
        for (int j = 0; j < 4; j++)
#pragma unroll
            for (int c = 0; c < 4; c++) acc[i][j][c] = 0.0f;

    // ldmatrix addressing (constant per thread)
    const int lrow = lane & 15;
    const int lsel = lane >> 4;
    uint32_t arow[4], brow[2];
#pragma unroll
    for (int i = 0; i < 4; i++) arow[i] = (uint32_t)((warp_m * 64 + i * 16 + lrow) * 128);
#pragma unroll
    for (int j = 0; j < 2; j++) brow[j] = (uint32_t)((warp_n * 32 + j * 16 + lrow) * 128);
    const uint32_t kbase0 = (uint32_t)(lsel * 16);

    // ---- prologue: tile 0 ----
    ldg_tile(0);
    sts_tile(0);
    __syncthreads();

    // ---- mainloop ----
    for (int kt = 0; kt < NKIT; kt++) {
        const int cur = kt & 1;
        const bool more = (kt + 1 < NKIT);
        if (more) ldg_tile(kt + 1);       // LDG latency hides under MMAs

        const uint32_t base  = sbase + SM_TILES + cur * BUF_BYTES;
        const uint32_t a_hi = base + OFF_A_HI, a_lo = base + OFF_A_LO;
        const uint32_t b_hi = base + OFF_B_HI, b_lo = base + OFF_B_LO;

#pragma unroll
        for (int ks = 0; ks < 4; ks++) {
            const uint32_t koff = kbase0 + ks * 32;
            uint32_t ah[4][4], al[4][4], bh[2][4], bl[2][4];
#pragma unroll
            for (int i = 0; i < 4; i++) {
                ldsm4(ah[i], a_hi + SWZ(arow[i] + koff));
                ldsm4(al[i], a_lo + SWZ(arow[i] + koff));
            }
#pragma unroll
            for (int j = 0; j < 2; j++) {
                ldsm4(bh[j], b_hi + SWZ(brow[j] + koff));
                ldsm4(bl[j], b_lo + SWZ(brow[j] + koff));
            }
#pragma unroll
            for (int i = 0; i < 4; i++) {
#pragma unroll
                for (int jj = 0; jj < 4; jj++) {
                    const int j = jj >> 1, s = jj & 1;
                    mma_bf16(acc[i][jj], ah[i], bh[j][s], bh[j][s + 2]);
                    mma_bf16(acc[i][jj], ah[i], bl[j][s], bl[j][s + 2]);
                    mma_bf16(acc[i][jj], al[i], bh[j][s], bh[j][s + 2]);
                }
            }
        }

        if (more) sts_tile(cur ^ 1);
        __syncthreads();
    }

    // ---- epilogue: add bias, scatter rows to token positions ----
    const int gid = lane >> 2;     // 0..7
    const int qid = lane & 3;      // 0..3
#pragma unroll
    for (int i = 0; i < 4; i++) {
#pragma unroll
        for (int h = 0; h < 2; h++) {
            int row = warp_m * 64 + i * 16 + gid + h * 8;   // row within tile
            if (m0 + row < ne) {
                int tok = rs[row];
                float* dst = out + (size_t)tok * D_DIM + n0;
#pragma unroll
                for (int jj = 0; jj < 4; jj++) {
                    int nt = warp_n * 32 + jj * 8 + qid * 2;
                    float2 v;
                    v.x = acc[i][jj][h * 2 + 0] + bias_s[nt + 0];
                    v.y = acc[i][jj][h * 2 + 1] + bias_s[nt + 1];
                    *reinterpret_cast<float2*>(dst + nt) = v;
                }
            }
        }
    }
}

// ---------------------------------------------------------------------------
// Launch
// ---------------------------------------------------------------------------
extern "C" void kernel_launch(void* const* d_in, const int* in_sizes, int n_in,
                              void* d_out, int out_size) {
    const float* x  = (const float*)d_in[0];   // [8192, 1024]
    const float* y  = (const float*)d_in[1];   // [8192, 1024]
    const float* We = (const float*)d_in[2];   // [8, 2048, 2048]
    const float* be = (const float*)d_in[3];   // [8, 2048]
    const float* gW = (const float*)d_in[4];   // [8, 2048]
    const float* gb = (const float*)d_in[5];   // [8]
    float* out = (float*)d_out;                // [8192, 2048]

    cudaFuncSetAttribute(moe_gemm_mma,
                         cudaFuncAttributeMaxDynamicSharedMemorySize, SMEM_TOTAL);

    zero_cnt_kernel<<<1, 32>>>();
    gate_kernel<<<(B_TOK * 32) / 256, 256>>>(x, y, gW, gb);

    dim3 grid(B_TOK / BM, D_DIM / BN, N_EXP);
    moe_gemm_mma<<<grid, THREADS, SMEM_TOTAL>>>(x, y, We, be, out);
}

// round 5
// speedup vs baseline: 1.8140x; 1.0002x over previous
#include <cuda_runtime.h>
#include <cuda_bf16.h>
#include <cstdint>

// ---------------------------------------------------------------------------
// SparseMoE_2250562863537:
//   B=8192 tokens, inp = concat(x[.,1024], y[.,1024]) => D=2048, 8 experts,
//   K=1 top-k => softmax over one logit == 1.0
//   => out[b] = We[e_b] @ inp[b] + be[e_b],  e_b = argmax(gW @ inp[b] + gb)
//
// NOTE: build pipeline targets PTX .target sm_103 (no 'a') => tcgen05 is NOT
// available. Use legacy mma.sync.m16n8k16 (bf16, sm_80 baseline) + ldmatrix.
// Precision: fp32 operands split to bf16 hi/lo; 3 passes hi*hi+hi*lo+lo*hi,
// fp32 register accumulators => rel err ~1e-5.
// ---------------------------------------------------------------------------
#define B_TOK   8192
#define L_DIM   1024
#define D_DIM   2048
#define N_EXP   8

#define BM      128
#define BN      128
#define BK      64
#define NKIT    (D_DIM / BK)       // 32
#define THREADS 256                // 8 warps: 2 (m) x 4 (n), warp tile 64x32

// Scratch (device globals — no allocs allowed)
__device__ int g_cnt[N_EXP];
__device__ int g_list[N_EXP * B_TOK];

// ---------------------------------------------------------------------------
// SMEM layout
//   [0,512)    rows[128]
//   [512,1024) bias[128]
//   [1024,...) 2 x 64KB tile buffers, each: A_hi|A_lo|B_hi|B_lo (16KB each)
//   tiles are bf16 [128 rows][64 cols], 128B rows, SW128 xor swizzle
// ---------------------------------------------------------------------------
#define SM_ROWS    0
#define SM_BIAS    512
#define SM_TILES   1024
#define BUF_BYTES  65536
#define OFF_A_HI   0
#define OFF_A_LO   16384
#define OFF_B_HI   32768
#define OFF_B_LO   49152
#define SMEM_TOTAL (SM_TILES + 2 * BUF_BYTES)   // 132096 bytes

#define SWZ(b) ((b) ^ (((b) >> 3) & 0x70))

// ---------------------------------------------------------------------------
// helpers
// ---------------------------------------------------------------------------
__device__ __forceinline__ uint32_t smem_u32(const void* p) {
    uint32_t a;
    asm("{ .reg .u64 t; cvta.to.shared.u64 t, %1; cvt.u32.u64 %0, t; }"
        : "=r"(a) : "l"(p));
    return a;
}

__device__ __forceinline__ void ldsm4(uint32_t* r, uint32_t addr) {
    asm volatile("ldmatrix.sync.aligned.m8n8.x4.shared.b16 {%0,%1,%2,%3}, [%4];"
                 : "=r"(r[0]), "=r"(r[1]), "=r"(r[2]), "=r"(r[3]) : "r"(addr));
}

__device__ __forceinline__ void mma_bf16(float* c, const uint32_t* a,
                                         uint32_t b0, uint32_t b1) {
    asm volatile("mma.sync.aligned.m16n8k16.row.col.f32.bf16.bf16.f32 "
                 "{%0,%1,%2,%3}, {%4,%5,%6,%7}, {%8,%9}, {%0,%1,%2,%3};"
                 : "+f"(c[0]), "+f"(c[1]), "+f"(c[2]), "+f"(c[3])
                 : "r"(a[0]), "r"(a[1]), "r"(a[2]), "r"(a[3]),
                   "r"(b0), "r"(b1));
}

// split fp32x4 -> (hi,lo) bf16x2 pairs
__device__ __forceinline__ void split4(float4 v, uint2& hi, uint2& lo) {
    __nv_bfloat16 h0 = __float2bfloat16(v.x);
    __nv_bfloat16 h1 = __float2bfloat16(v.y);
    __nv_bfloat16 h2 = __float2bfloat16(v.z);
    __nv_bfloat16 h3 = __float2bfloat16(v.w);
    __nv_bfloat16 l0 = __float2bfloat16(v.x - __bfloat162float(h0));
    __nv_bfloat16 l1 = __float2bfloat16(v.y - __bfloat162float(h1));
    __nv_bfloat16 l2 = __float2bfloat16(v.z - __bfloat162float(h2));
    __nv_bfloat16 l3 = __float2bfloat16(v.w - __bfloat162float(h3));
    hi.x = (uint32_t)__bfloat16_as_ushort(h0) | ((uint32_t)__bfloat16_as_ushort(h1) << 16);
    hi.y = (uint32_t)__bfloat16_as_ushort(h2) | ((uint32_t)__bfloat16_as_ushort(h3) << 16);
    lo.x = (uint32_t)__bfloat16_as_ushort(l0) | ((uint32_t)__bfloat16_as_ushort(l1) << 16);
    lo.y = (uint32_t)__bfloat16_as_ushort(l2) | ((uint32_t)__bfloat16_as_ushort(l3) << 16);
}

// ---------------------------------------------------------------------------
// Kernel 0: zero counters
// ---------------------------------------------------------------------------
__global__ void zero_cnt_kernel() {
    if (threadIdx.x < N_EXP) g_cnt[threadIdx.x] = 0;
}

// ---------------------------------------------------------------------------
// Kernel 1: gate + argmax + scatter (proven in R2, rel_err 8e-7)
// ---------------------------------------------------------------------------
__global__ void gate_kernel(const float* __restrict__ x,
                            const float* __restrict__ y,
                            const float* __restrict__ gW,
                            const float* __restrict__ gb) {
    int gwarp = (blockIdx.x * blockDim.x + threadIdx.x) >> 5;
    int lane  = threadIdx.x & 31;
    if (gwarp >= B_TOK) return;
    int tok = gwarp;

    float acc[N_EXP];
#pragma unroll
    for (int e = 0; e < N_EXP; e++) acc[e] = 0.0f;

    for (int k = lane; k < D_DIM; k += 32) {
        float v = (k < L_DIM) ? x[(size_t)tok * L_DIM + k]
                              : y[(size_t)tok * L_DIM + (k - L_DIM)];
#pragma unroll
        for (int e = 0; e < N_EXP; e++)
            acc[e] = fmaf(v, gW[e * D_DIM + k], acc[e]);
    }
#pragma unroll
    for (int e = 0; e < N_EXP; e++) {
#pragma unroll
        for (int o = 16; o > 0; o >>= 1)
            acc[e] += __shfl_xor_sync(0xFFFFFFFFu, acc[e], o);
    }
    if (lane == 0) {
        float best = acc[0] + gb[0];
        int   bidx = 0;
#pragma unroll
        for (int e = 1; e < N_EXP; e++) {
            float v = acc[e] + gb[e];
            if (v > best) { best = v; bidx = e; }
        }
        int pos = atomicAdd(&g_cnt[bidx], 1);
        g_list[bidx * B_TOK + pos] = tok;
    }
}

// ---------------------------------------------------------------------------
// Kernel 2: grouped GEMM, mma.sync bf16x3, fp32 reg accumulators
// ---------------------------------------------------------------------------
__global__ __launch_bounds__(THREADS, 1)
void moe_gemm_mma(const float* __restrict__ x,
                  const float* __restrict__ y,
                  const float* __restrict__ We,
                  const float* __restrict__ be,
                  float* __restrict__ out) {
    const int e  = blockIdx.z;
    const int ne = g_cnt[e];
    const int m0 = blockIdx.x * BM;
    if (m0 >= ne) return;
    const int n0 = blockIdx.y * BN;

    extern __shared__ char smem[];
    const uint32_t sbase = smem_u32(smem);
    int*   rs     = (int*)(smem + SM_ROWS);
    float* bias_s = (float*)(smem + SM_BIAS);

    const int tid    = threadIdx.x;
    const int wid    = tid >> 5;
    const int lane   = tid & 31;
    const int warp_m = wid & 1;    // 0..1 -> m offset 0 / 64
    const int warp_n = wid >> 1;   // 0..3 -> n offset 0/32/64/96

    // ---- stage token rows + bias ----
    if (tid < BM) {
        int gm = m0 + tid;
        rs[tid]     = (gm < ne) ? g_list[e * B_TOK + gm] : g_list[e * B_TOK];
        bias_s[tid] = be[e * D_DIM + n0 + tid];
    }
    __syncthreads();

    const float* W = We + (size_t)e * D_DIM * D_DIM + (size_t)n0 * D_DIM;

    // per-thread tile-load geometry: 16 float4/thread/iter (8 A + 8 B)
    const int ldr  = tid >> 4;          // used with +16*u below? no: see loop
    (void)ldr;

    float4 av[8], bv[8];

    // ---- tile loaders ----
    auto ldg_tile = [&](int kt) {
        const int k0 = kt * BK;
        const float* xa  = (k0 < L_DIM) ? x : y;
        const int   acol = (k0 < L_DIM) ? k0 : (k0 - L_DIM);
#pragma unroll
        for (int u = 0; u < 8; u++) {
            int f  = u * THREADS + tid;   // 0..2047
            int r  = f >> 4;              // row 0..127
            int c4 = f & 15;              // float4 col 0..15
            av[u] = *reinterpret_cast<const float4*>(
                xa + (size_t)rs[r] * L_DIM + acol + c4 * 4);
            bv[u] = *reinterpret_cast<const float4*>(
                W + (size_t)r * D_DIM + k0 + c4 * 4);
        }
    };
    auto sts_tile = [&](int b) {
        char* bufc = smem + SM_TILES + b * BUF_BYTES;
#pragma unroll
        for (int u = 0; u < 8; u++) {
            int f  = u * THREADS + tid;
            int r  = f >> 4;
            int c4 = f & 15;
            uint32_t boff = SWZ((uint32_t)(r * 128 + c4 * 8));
            uint2 hv, lv;
            split4(av[u], hv, lv);
            *reinterpret_cast<uint2*>(bufc + OFF_A_HI + boff) = hv;
            *reinterpret_cast<uint2*>(bufc + OFF_A_LO + boff) = lv;
            split4(bv[u], hv, lv);
            *reinterpret_cast<uint2*>(bufc + OFF_B_HI + boff) = hv;
            *reinterpret_cast<uint2*>(bufc + OFF_B_LO + boff) = lv;
        }
    };

    // ---- accumulators ----
    float acc[4][4][4];
#pragma unroll
    for (int i = 0; i < 4; i++)
#pragma unroll
        for (int j = 0; j < 4; j++)
#pragma unroll
            for (int c = 0; c < 4; c++) acc[i][j][c] = 0.0f;

    // ldmatrix addressing (constant per thread)
    const int lrow = lane & 15;
    const int lsel = lane >> 4;
    uint32_t arow[4], brow[2];
#pragma unroll
    for (int i = 0; i < 4; i++) arow[i] = (uint32_t)((warp_m * 64 + i * 16 + lrow) * 128);
#pragma unroll
    for (int j = 0; j < 2; j++) brow[j] = (uint32_t)((warp_n * 32 + j * 16 + lrow) * 128);
    const uint32_t kbase0 = (uint32_t)(lsel * 16);

    // ---- prologue: tile 0 ----
    ldg_tile(0);
    sts_tile(0);
    __syncthreads();

    // ---- mainloop ----
    for (int kt = 0; kt < NKIT; kt++) {
        const int cur = kt & 1;
        const bool more = (kt + 1 < NKIT);
        if (more) ldg_tile(kt + 1);       // LDG latency hides under MMAs

        const uint32_t base  = sbase + SM_TILES + cur * BUF_BYTES;
        const uint32_t a_hi = base + OFF_A_HI, a_lo = base + OFF_A_LO;
        const uint32_t b_hi = base + OFF_B_HI, b_lo = base + OFF_B_LO;

#pragma unroll
        for (int ks = 0; ks < 4; ks++) {
            const uint32_t koff = kbase0 + ks * 32;
            uint32_t ah[4][4], al[4][4], bh[2][4], bl[2][4];
#pragma unroll
            for (int i = 0; i < 4; i++) {
                ldsm4(ah[i], a_hi + SWZ(arow[i] + koff));
                ldsm4(al[i], a_lo + SWZ(arow[i] + koff));
            }
#pragma unroll
            for (int j = 0; j < 2; j++) {
                ldsm4(bh[j], b_hi + SWZ(brow[j] + koff));
                ldsm4(bl[j], b_lo + SWZ(brow[j] + koff));
            }
#pragma unroll
            for (int i = 0; i < 4; i++) {
#pragma unroll
                for (int jj = 0; jj < 4; jj++) {
                    const int j = jj >> 1, s = jj & 1;
                    mma_bf16(acc[i][jj], ah[i], bh[j][s], bh[j][s + 2]);
                    mma_bf16(acc[i][jj], ah[i], bl[j][s], bl[j][s + 2]);
                    mma_bf16(acc[i][jj], al[i], bh[j][s], bh[j][s + 2]);
                }
            }
        }

        if (more) sts_tile(cur ^ 1);
        __syncthreads();
    }

    // ---- epilogue: add bias, scatter rows to token positions ----
    const int gid = lane >> 2;     // 0..7
    const int qid = lane & 3;      // 0..3
#pragma unroll
    for (int i = 0; i < 4; i++) {
#pragma unroll
        for (int h = 0; h < 2; h++) {
            int row = warp_m * 64 + i * 16 + gid + h * 8;   // row within tile
            if (m0 + row < ne) {
                int tok = rs[row];
                float* dst = out + (size_t)tok * D_DIM + n0;
#pragma unroll
                for (int jj = 0; jj < 4; jj++) {
                    int nt = warp_n * 32 + jj * 8 + qid * 2;
                    float2 v;
                    v.x = acc[i][jj][h * 2 + 0] + bias_s[nt + 0];
                    v.y = acc[i][jj][h * 2 + 1] + bias_s[nt + 1];
                    *reinterpret_cast<float2*>(dst + nt) = v;
                }
            }
        }
    }
}

// ---------------------------------------------------------------------------
// Launch
// ---------------------------------------------------------------------------
extern "C" void kernel_launch(void* const* d_in, const int* in_sizes, int n_in,
                              void* d_out, int out_size) {
    const float* x  = (const float*)d_in[0];   // [8192, 1024]
    const float* y  = (const float*)d_in[1];   // [8192, 1024]
    const float* We = (const float*)d_in[2];   // [8, 2048, 2048]
    const float* be = (const float*)d_in[3];   // [8, 2048]
    const float* gW = (const float*)d_in[4];   // [8, 2048]
    const float* gb = (const float*)d_in[5];   // [8]
    float* out = (float*)d_out;                // [8192, 2048]

    cudaFuncSetAttribute(moe_gemm_mma,
                         cudaFuncAttributeMaxDynamicSharedMemorySize, SMEM_TOTAL);

    zero_cnt_kernel<<<1, 32>>>();
    gate_kernel<<<(B_TOK * 32) / 256, 256>>>(x, y, gW, gb);

    dim3 grid(B_TOK / BM, D_DIM / BN, N_EXP);
    moe_gemm_mma<<<grid, THREADS, SMEM_TOTAL>>>(x, y, We, be, out);
}

// round 6
// speedup vs baseline: 2.3386x; 1.2892x over previous
#include <cuda_runtime.h>
#include <cuda_bf16.h>
#include <cstdint>

// ---------------------------------------------------------------------------
// SparseMoE_2250562863537 (fixed shapes):
//   B=8192 tokens, inp = concat(x,y) => D=2048, 8 experts, K=1 top-k
//   K=1 => softmax(single logit)==1 => out[b] = We[e_b] @ inp[b] + be[e_b]
//
// Build targets PTX sm_103 (no 'a') => no tcgen05. Use mma.sync.m16n8k16.bf16.
// Precision: fp32 = bf16_hi + bf16_lo, 3 passes (hh + hl + lh), fp32 acc.
// R6: pre-split operands ONCE into device-global bf16 hi/lo scratch; GEMM
// mainloop is pure cp.async -> ldmatrix -> HMMA (no fp32->bf16 conversion).
// ---------------------------------------------------------------------------
#define B_TOK   8192
#define L_DIM   1024
#define D_DIM   2048
#define N_EXP   8

#define BM      128
#define BN      128
#define BK      64
#define NKIT    (D_DIM / BK)       // 32
#define THREADS 256                // 8 warps: 2(m) x 4(n), warp tile 64x32
#define STAGES  3

// Scratch (device globals — allocation is forbidden)
__device__ int g_cnt[N_EXP];
__device__ int g_list[N_EXP * B_TOK];
__device__ __nv_bfloat16 g_Ahi[B_TOK * D_DIM];            // 32 MB
__device__ __nv_bfloat16 g_Alo[B_TOK * D_DIM];            // 32 MB
__device__ __nv_bfloat16 g_Whi[N_EXP * D_DIM * D_DIM];    // 64 MB
__device__ __nv_bfloat16 g_Wlo[N_EXP * D_DIM * D_DIM];    // 64 MB

// ---------------------------------------------------------------------------
// SMEM layout: header + STAGES x 64KB buffers (A_hi|A_lo|B_hi|B_lo 16KB each)
// tiles bf16 [128 rows][64 cols], 128B rows, SW128 xor swizzle
// ---------------------------------------------------------------------------
#define SM_ROWS    0
#define SM_BIAS    512
#define SM_TILES   1024
#define BUF_BYTES  65536
#define OFF_A_HI   0
#define OFF_A_LO   16384
#define OFF_B_HI   32768
#define OFF_B_LO   49152
#define SMEM_TOTAL (SM_TILES + STAGES * BUF_BYTES)   // 197632

#define SWZ(b) ((b) ^ (((b) >> 3) & 0x70))

// ---------------------------------------------------------------------------
// helpers
// ---------------------------------------------------------------------------
__device__ __forceinline__ uint32_t smem_u32(const void* p) {
    uint32_t a;
    asm("{ .reg .u64 t; cvta.to.shared.u64 t, %1; cvt.u32.u64 %0, t; }"
        : "=r"(a) : "l"(p));
    return a;
}

#define CP_ASYNC16(dst, src) \
    asm volatile("cp.async.cg.shared.global [%0], [%1], 16;" \
                 :: "r"(dst), "l"(src) : "memory")
#define CP_COMMIT() asm volatile("cp.async.commit_group;" ::: "memory")
#define CP_WAIT(n)  asm volatile("cp.async.wait_group %0;" :: "n"(n) : "memory")

__device__ __forceinline__ void ldsm4(uint32_t* r, uint32_t addr) {
    asm volatile("ldmatrix.sync.aligned.m8n8.x4.shared.b16 {%0,%1,%2,%3}, [%4];"
                 : "=r"(r[0]), "=r"(r[1]), "=r"(r[2]), "=r"(r[3]) : "r"(addr));
}

__device__ __forceinline__ void mma_bf16(float* c, const uint32_t* a,
                                         uint32_t b0, uint32_t b1) {
    asm volatile("mma.sync.aligned.m16n8k16.row.col.f32.bf16.bf16.f32 "
                 "{%0,%1,%2,%3}, {%4,%5,%6,%7}, {%8,%9}, {%0,%1,%2,%3};"
                 : "+f"(c[0]), "+f"(c[1]), "+f"(c[2]), "+f"(c[3])
                 : "r"(a[0]), "r"(a[1]), "r"(a[2]), "r"(a[3]),
                   "r"(b0), "r"(b1));
}

__device__ __forceinline__ void split4(float4 v, uint2& hi, uint2& lo) {
    __nv_bfloat16 h0 = __float2bfloat16(v.x);
    __nv_bfloat16 h1 = __float2bfloat16(v.y);
    __nv_bfloat16 h2 = __float2bfloat16(v.z);
    __nv_bfloat16 h3 = __float2bfloat16(v.w);
    __nv_bfloat16 l0 = __float2bfloat16(v.x - __bfloat162float(h0));
    __nv_bfloat16 l1 = __float2bfloat16(v.y - __bfloat162float(h1));
    __nv_bfloat16 l2 = __float2bfloat16(v.z - __bfloat162float(h2));
    __nv_bfloat16 l3 = __float2bfloat16(v.w - __bfloat162float(h3));
    hi.x = (uint32_t)__bfloat16_as_ushort(h0) | ((uint32_t)__bfloat16_as_ushort(h1) << 16);
    hi.y = (uint32_t)__bfloat16_as_ushort(h2) | ((uint32_t)__bfloat16_as_ushort(h3) << 16);
    lo.x = (uint32_t)__bfloat16_as_ushort(l0) | ((uint32_t)__bfloat16_as_ushort(l1) << 16);
    lo.y = (uint32_t)__bfloat16_as_ushort(l2) | ((uint32_t)__bfloat16_as_ushort(l3) << 16);
}

// ---------------------------------------------------------------------------
// Kernel 0: zero counters
// ---------------------------------------------------------------------------
__global__ void zero_cnt_kernel() {
    if (threadIdx.x < N_EXP) g_cnt[threadIdx.x] = 0;
}

// ---------------------------------------------------------------------------
// Kernel 1a: pre-split inp = concat(x,y) -> g_Ahi/g_Alo
// ---------------------------------------------------------------------------
__global__ __launch_bounds__(256)
void prep_inp(const float* __restrict__ x, const float* __restrict__ y) {
    int f = blockIdx.x * blockDim.x + threadIdx.x;   // float4 id
    if (f >= B_TOK * D_DIM / 4) return;
    int row = f >> 9;                // /512 float4 per row
    int c4  = f & 511;
    int col = c4 * 4;
    const float* src = (col < L_DIM)
        ? (x + (size_t)row * L_DIM + col)
        : (y + (size_t)row * L_DIM + (col - L_DIM));
    float4 v = *reinterpret_cast<const float4*>(src);
    uint2 hv, lv;
    split4(v, hv, lv);
    size_t o = (size_t)row * D_DIM + col;
    *reinterpret_cast<uint2*>(g_Ahi + o) = hv;
    *reinterpret_cast<uint2*>(g_Alo + o) = lv;
}

// ---------------------------------------------------------------------------
// Kernel 1b: pre-split We -> g_Whi/g_Wlo
// ---------------------------------------------------------------------------
__global__ __launch_bounds__(256)
void prep_w(const float* __restrict__ We) {
    size_t f = (size_t)blockIdx.x * blockDim.x + threadIdx.x;  // float4 id
    if (f >= (size_t)N_EXP * D_DIM * D_DIM / 4) return;
    float4 v = *reinterpret_cast<const float4*>(We + f * 4);
    uint2 hv, lv;
    split4(v, hv, lv);
    *reinterpret_cast<uint2*>(g_Whi + f * 4) = hv;
    *reinterpret_cast<uint2*>(g_Wlo + f * 4) = lv;
}

// ---------------------------------------------------------------------------
// Kernel 2: gate + argmax + scatter (proven: rel_err 8e-7 contribution)
// ---------------------------------------------------------------------------
__global__ void gate_kernel(const float* __restrict__ x,
                            const float* __restrict__ y,
                            const float* __restrict__ gW,
                            const float* __restrict__ gb) {
    int gwarp = (blockIdx.x * blockDim.x + threadIdx.x) >> 5;
    int lane  = threadIdx.x & 31;
    if (gwarp >= B_TOK) return;
    int tok = gwarp;

    float acc[N_EXP];
#pragma unroll
    for (int e = 0; e < N_EXP; e++) acc[e] = 0.0f;
    for (int k = lane; k < D_DIM; k += 32) {
        float v = (k < L_DIM) ? x[(size_t)tok * L_DIM + k]
                              : y[(size_t)tok * L_DIM + (k - L_DIM)];
#pragma unroll
        for (int e = 0; e < N_EXP; e++)
            acc[e] = fmaf(v, gW[e * D_DIM + k], acc[e]);
    }
#pragma unroll
    for (int e = 0; e < N_EXP; e++) {
#pragma unroll
        for (int o = 16; o > 0; o >>= 1)
            acc[e] += __shfl_xor_sync(0xFFFFFFFFu, acc[e], o);
    }
    if (lane == 0) {
        float best = acc[0] + gb[0];
        int   bidx = 0;
#pragma unroll
        for (int e = 1; e < N_EXP; e++) {
            float v = acc[e] + gb[e];
            if (v > best) { best = v; bidx = e; }
        }
        int pos = atomicAdd(&g_cnt[bidx], 1);
        g_list[bidx * B_TOK + pos] = tok;
    }
}

// ---------------------------------------------------------------------------
// Kernel 3: grouped GEMM, pure bf16x3 HMMA pipeline (cp.async, 3 stages)
// ---------------------------------------------------------------------------
__global__ __launch_bounds__(THREADS, 1)
void moe_gemm_mma(const float* __restrict__ be, float* __restrict__ out) {
    const int e  = blockIdx.z;
    const int ne = g_cnt[e];
    const int m0 = blockIdx.x * BM;
    if (m0 >= ne) return;
    const int n0 = blockIdx.y * BN;

    extern __shared__ char smem[];
    const uint32_t sbase = smem_u32(smem);
    int*   rs     = (int*)(smem + SM_ROWS);
    float* bias_s = (float*)(smem + SM_BIAS);

    const int tid    = threadIdx.x;
    const int wid    = tid >> 5;
    const int lane   = tid & 31;
    const int warp_m = wid & 1;
    const int warp_n = wid >> 1;

    if (tid < BM) {
        int gm = m0 + tid;
        rs[tid]     = (gm < ne) ? g_list[e * B_TOK + gm] : g_list[e * B_TOK];
        bias_s[tid] = be[e * D_DIM + n0 + tid];
    }
    __syncthreads();

    // ---- per-thread cp.async geometry: 4 chunks per tile, 4 tiles ----
    // chunk id f = u*256+tid : row r = f>>3 (0..127), 16B col c = f&7
    const char* a_hi_base[4];
    const char* a_lo_base[4];
    const char* b_hi_base[4];
    const char* b_lo_base[4];
    uint32_t dst_off[4];
#pragma unroll
    for (int u = 0; u < 4; u++) {
        int f = u * THREADS + tid;
        int r = f >> 3;
        int c = f & 7;
        int tok = rs[r];
        size_t ao = ((size_t)tok * D_DIM + c * 8) * 2;          // bytes
        size_t bo = (((size_t)e * D_DIM + n0 + r) * D_DIM + c * 8) * 2;
        a_hi_base[u] = (const char*)g_Ahi + ao;
        a_lo_base[u] = (const char*)g_Alo + ao;
        b_hi_base[u] = (const char*)g_Whi + bo;
        b_lo_base[u] = (const char*)g_Wlo + bo;
        dst_off[u] = SWZ((uint32_t)(r * 128 + c * 16));
    }

    auto issue = [&](int kt) {
        const uint32_t buf = sbase + SM_TILES + (kt % STAGES) * BUF_BYTES;
        const size_t kb = (size_t)(kt * BK) * 2;   // byte offset along K
#pragma unroll
        for (int u = 0; u < 4; u++) {
            CP_ASYNC16(buf + OFF_A_HI + dst_off[u], a_hi_base[u] + kb);
            CP_ASYNC16(buf + OFF_A_LO + dst_off[u], a_lo_base[u] + kb);
            CP_ASYNC16(buf + OFF_B_HI + dst_off[u], b_hi_base[u] + kb);
            CP_ASYNC16(buf + OFF_B_LO + dst_off[u], b_lo_base[u] + kb);
        }
        CP_COMMIT();
    };

    // ---- accumulators ----
    float acc[4][4][4];
#pragma unroll
    for (int i = 0; i < 4; i++)
#pragma unroll
        for (int j = 0; j < 4; j++)
#pragma unroll
            for (int c = 0; c < 4; c++) acc[i][j][c] = 0.0f;

    // ldmatrix addressing
    const int lrow = lane & 15;
    const int lsel = lane >> 4;
    uint32_t arow[4], brow[2];
#pragma unroll
    for (int i = 0; i < 4; i++) arow[i] = (uint32_t)((warp_m * 64 + i * 16 + lrow) * 128);
#pragma unroll
    for (int j = 0; j < 2; j++) brow[j] = (uint32_t)((warp_n * 32 + j * 16 + lrow) * 128);
    const uint32_t kbase0 = (uint32_t)(lsel * 16);

    // ---- prologue: stages 0..STAGES-2 ----
    issue(0);
    issue(1);

    // ---- mainloop ----
    for (int kt = 0; kt < NKIT; kt++) {
        CP_WAIT(STAGES - 2);       // stage kt landed
        __syncthreads();           // + everyone done computing stage kt-1

        if (kt + STAGES - 1 < NKIT) issue(kt + STAGES - 1);

        const uint32_t base = sbase + SM_TILES + (kt % STAGES) * BUF_BYTES;
        const uint32_t a_hi = base + OFF_A_HI, a_lo = base + OFF_A_LO;
        const uint32_t b_hi = base + OFF_B_HI, b_lo = base + OFF_B_LO;

#pragma unroll
        for (int ks = 0; ks < 4; ks++) {
            const uint32_t koff = kbase0 + ks * 32;
            uint32_t ah[4][4], al[4][4], bh[2][4], bl[2][4];
#pragma unroll
            for (int i = 0; i < 4; i++) {
                ldsm4(ah[i], a_hi + SWZ(arow[i] + koff));
                ldsm4(al[i], a_lo + SWZ(arow[i] + koff));
            }
#pragma unroll
            for (int j = 0; j < 2; j++) {
                ldsm4(bh[j], b_hi + SWZ(brow[j] + koff));
                ldsm4(bl[j], b_lo + SWZ(brow[j] + koff));
            }
            // 3 passes OUTER: 16 independent MMAs between reuses of each acc
#pragma unroll
            for (int pass = 0; pass < 3; pass++) {
#pragma unroll
                for (int i = 0; i < 4; i++) {
#pragma unroll
                    for (int jj = 0; jj < 4; jj++) {
                        const int j = jj >> 1, s = jj & 1;
                        const uint32_t* a = (pass == 2) ? al[i] : ah[i];
                        const uint32_t b0 = (pass == 1) ? bl[j][s]     : bh[j][s];
                        const uint32_t b1 = (pass == 1) ? bl[j][s + 2] : bh[j][s + 2];
                        mma_bf16(acc[i][jj], a, b0, b1);
                    }
                }
            }
        }
    }

    // ---- epilogue: add bias, scatter to token rows ----
    const int gid = lane >> 2;
    const int qid = lane & 3;
#pragma unroll
    for (int i = 0; i < 4; i++) {
#pragma unroll
        for (int h = 0; h < 2; h++) {
            int row = warp_m * 64 + i * 16 + gid + h * 8;
            if (m0 + row < ne) {
                int tok = rs[row];
                float* dst = out + (size_t)tok * D_DIM + n0;
#pragma unroll
                for (int jj = 0; jj < 4; jj++) {
                    int nt = warp_n * 32 + jj * 8 + qid * 2;
                    float2 v;
                    v.x = acc[i][jj][h * 2 + 0] + bias_s[nt + 0];
                    v.y = acc[i][jj][h * 2 + 1] + bias_s[nt + 1];
                    *reinterpret_cast<float2*>(dst + nt) = v;
                }
            }
        }
    }
}

// ---------------------------------------------------------------------------
// Launch
// ---------------------------------------------------------------------------
extern "C" void kernel_launch(void* const* d_in, const int* in_sizes, int n_in,
                              void* d_out, int out_size) {
    const float* x  = (const float*)d_in[0];
    const float* y  = (const float*)d_in[1];
    const float* We = (const float*)d_in[2];
    const float* be = (const float*)d_in[3];
    const float* gW = (const float*)d_in[4];
    const float* gb = (const float*)d_in[5];
    float* out = (float*)d_out;

    cudaFuncSetAttribute(moe_gemm_mma,
                         cudaFuncAttributeMaxDynamicSharedMemorySize, SMEM_TOTAL);

    zero_cnt_kernel<<<1, 32>>>();
    gate_kernel<<<(B_TOK * 32) / 256, 256>>>(x, y, gW, gb);
    prep_inp<<<(B_TOK * D_DIM / 4 + 255) / 256, 256>>>(x, y);
    {
        size_t nf4 = (size_t)N_EXP * D_DIM * D_DIM / 4;
        prep_w<<<(unsigned)((nf4 + 255) / 256), 256>>>(We);
    }

    dim3 grid(B_TOK / BM, D_DIM / BN, N_EXP);
    moe_gemm_mma<<<grid, THREADS, SMEM_TOTAL>>>(be, out);
}